// round 13
// baseline (speedup 1.0000x reference)
#include <cuda_runtime.h>
#include <float.h>
#include <math.h>

// Problem constants (fixed by reference setup_inputs)
#define BB 8
#define SS 4096
#define CC 1024
#define HH 64
#define NS 128          // S splits for partial reduction
#define SROWS (SS/NS)   // 32 rows per partial chunk

// Scratch (no allocations allowed in kernel_launch)
__device__ float g_psum[BB*NS*CC];
__device__ float g_pmax[BB*NS*CC];
__device__ int   g_pcnt[BB*NS];
__device__ float g_mean[BB*CC];
__device__ float g_max [BB*CC];
__device__ float g_hsum[BB*HH];
__device__ float g_a   [BB*CC];
__device__ unsigned g_bar = 0;   // monotonic grid-barrier ticket counter

#define ACC(v)  do { \
    sum.x += (v).x; sum.y += (v).y; sum.z += (v).z; sum.w += (v).w; \
    mx.x = fmaxf(mx.x, (v).x); mx.y = fmaxf(mx.y, (v).y);           \
    mx.z = fmaxf(mx.z, (v).z); mx.w = fmaxf(mx.w, (v).w); } while (0)

#define ACCSM(s, m) do { \
    sum.x += (s).x; sum.y += (s).y; sum.z += (s).z; sum.w += (s).w; \
    mx.x = fmaxf(mx.x, (m).x); mx.y = fmaxf(mx.y, (m).y);           \
    mx.z = fmaxf(mx.z, (m).z); mx.w = fmaxf(mx.w, (m).w); } while (0)

// Software grid barrier for a co-resident grid of nb blocks.
__device__ __forceinline__ void gridbar(unsigned nb) {
    __syncthreads();
    __threadfence();
    if (threadIdx.x == 0) {
        const unsigned t = atomicAdd(&g_bar, 1u);
        const unsigned target = (t / nb + 1u) * nb;
        while (*((volatile unsigned*)&g_bar) < target) { }
    }
    __syncthreads();
}

#define CP_ASYNC16(dst_u32, src_ptr) \
    asm volatile("cp.async.cg.shared.global [%0], [%1], 16;\n" \
                 :: "r"(dst_u32), "l"(src_ptr))
#define CP_COMMIT() asm volatile("cp.async.commit_group;\n")
#define CP_WAIT0()  asm volatile("cp.async.wait_group 0;\n" ::: "memory")

// ---------------------------------------------------------------------------
// Kernel 1: partial masked sum/max over a 32-row chunk, full 1024 channels.
// Ballot compaction, then cp.async batches of 8 rows into a smem row buffer.
// Each thread copies and reduces ONLY its own 16B slots -> no __syncthreads
// in the loop; 8 loads in flight per thread with zero register cost.
// grid (NS, BB) = 1024 blocks, 256 threads.
// ---------------------------------------------------------------------------
__global__ void k_partial(const float* __restrict__ x,
                          const int*   __restrict__ mask) {
    const int ns = blockIdx.x;
    const int b  = blockIdx.y;
    const int c4 = threadIdx.x;              // float4 index 0..255

    __shared__ int srows[SROWS];
    __shared__ int snv;
    __shared__ __align__(16) float buf[8][CC];   // 32 KB row buffer
    const int s0 = ns * SROWS;

    if (threadIdx.x < 32) {
        const int lane = threadIdx.x;
        const int m = mask[b * SS + s0 + lane];
        const unsigned bal = __ballot_sync(0xFFFFFFFFu, m != 0);
        if (m) srows[__popc(bal & ((1u << lane) - 1u))] = lane;
        if (lane == 0) {
            snv = __popc(bal);
            g_pcnt[b * NS + ns] = __popc(bal);
        }
    }
    __syncthreads();
    const int nv = snv;

    float4 sum = make_float4(0.f, 0.f, 0.f, 0.f);
    float4 mx  = make_float4(-FLT_MAX, -FLT_MAX, -FLT_MAX, -FLT_MAX);

    const float* xbase = x + ((size_t)b * SS + s0) * CC;
    const unsigned sdst =
        (unsigned)__cvta_generic_to_shared(&buf[0][0]) + (unsigned)c4 * 16u;

    for (int i = 0; i < nv; i += 8) {
        int m = nv - i; if (m > 8) m = 8;
        #pragma unroll
        for (int r = 0; r < 8; r++) {
            if (r < m) {
                const float* src = xbase + (size_t)srows[i + r] * CC + c4 * 4;
                CP_ASYNC16(sdst + (unsigned)r * (CC * 4u), src);
            }
        }
        CP_COMMIT();
        CP_WAIT0();
        #pragma unroll
        for (int r = 0; r < 8; r++) {
            if (r < m) {
                float4 v = *reinterpret_cast<const float4*>(&buf[r][c4 * 4]);
                ACC(v);
            }
        }
    }

    reinterpret_cast<float4*>(g_psum + (b * NS + ns) * CC)[c4] = sum;
    reinterpret_cast<float4*>(g_pmax + (b * NS + ns) * CC)[c4] = mx;
}

// ---------------------------------------------------------------------------
// Kernel 2 (fused tail with grid barriers): fold -> MLP1 -> MLP2.
// grid (8, BB) = 64 blocks, 256 threads.  (R12-measured: ~5 us)
// ---------------------------------------------------------------------------
#define NBLK (8*BB)

__global__ void __launch_bounds__(256)
k_tail(const float* __restrict__ W0,     // [H, C]
       const float* __restrict__ W1) {   // [C, H]
    const int chunk = blockIdx.x;        // 0..7
    const int b     = blockIdx.y;
    const int tid   = threadIdx.x;
    const int warp  = tid >> 5;
    const int lane  = tid & 31;

    __shared__ float4 ssum[8][32];
    __shared__ float4 smax4[8][32];
    __shared__ __align__(16) float smean[CC];
    __shared__ __align__(16) float smaxv[CC];
    __shared__ __align__(16) float sh[HH];
    __shared__ float  scount;

    // ---- Phase A: fold NS=128 partials for channels [chunk*128, +128) ----
    {
        const int g  = tid & 31;
        const int sl = tid >> 5;
        const int c4 = chunk * 32 + g;

        float4 sum = make_float4(0.f, 0.f, 0.f, 0.f);
        float4 mx  = make_float4(-FLT_MAX, -FLT_MAX, -FLT_MAX, -FLT_MAX);
        const float4* ps = reinterpret_cast<const float4*>(
            g_psum + (b * NS + sl * 16) * CC) + c4;
        const float4* pm = reinterpret_cast<const float4*>(
            g_pmax + (b * NS + sl * 16) * CC) + c4;
        #pragma unroll
        for (int k = 0; k < 16; k++) {
            float4 s = ps[(size_t)k * (CC / 4)];
            float4 m = pm[(size_t)k * (CC / 4)];
            ACCSM(s, m);
        }
        ssum[sl][g]  = sum;
        smax4[sl][g] = mx;

        if (tid < 32) {
            const int* pc = g_pcnt + b * NS;
            int c = pc[lane] + pc[lane + 32] + pc[lane + 64] + pc[lane + 96];
            #pragma unroll
            for (int off = 16; off > 0; off >>= 1)
                c += __shfl_xor_sync(0xFFFFFFFFu, c, off);
            if (lane == 0) scount = fmaxf((float)c, 1.0f);
        }
        __syncthreads();

        if (tid < 32) {
            const int g0 = tid;
            float4 sum2 = ssum[0][g0];
            float4 mx2  = smax4[0][g0];
            #pragma unroll
            for (int k = 1; k < 8; k++) {
                float4 s = ssum[k][g0];
                float4 m = smax4[k][g0];
                sum2.x += s.x; sum2.y += s.y; sum2.z += s.z; sum2.w += s.w;
                mx2.x = fmaxf(mx2.x, m.x); mx2.y = fmaxf(mx2.y, m.y);
                mx2.z = fmaxf(mx2.z, m.z); mx2.w = fmaxf(mx2.w, m.w);
            }
            const float inv = 1.0f / scount;
            sum2.x *= inv; sum2.y *= inv; sum2.z *= inv; sum2.w *= inv;
            reinterpret_cast<float4*>(g_mean + b * CC)[chunk * 32 + g0] = sum2;
            reinterpret_cast<float4*>(g_max  + b * CC)[chunk * 32 + g0] = mx2;
        }
    }

    gridbar(NBLK);

    // ---- Phase B: hidden units j = chunk*8 + warp for batch b -----------
    {
        {
            float4 S = reinterpret_cast<const float4*>(g_mean + b * CC)[tid];
            float4 M = reinterpret_cast<const float4*>(g_max  + b * CC)[tid];
            reinterpret_cast<float4*>(smean)[tid] = S;
            reinterpret_cast<float4*>(smaxv)[tid] = M;
        }
        __syncthreads();

        const int j = chunk * 8 + warp;
        const float* w = W0 + j * CC;
        float dm = 0.0f, dx = 0.0f;
        #pragma unroll 8
        for (int k = lane; k < CC; k += 32) {
            float wv = w[k];
            dm += wv * smean[k];
            dx += wv * smaxv[k];
        }
        #pragma unroll
        for (int off = 16; off > 0; off >>= 1) {
            dm += __shfl_xor_sync(0xFFFFFFFFu, dm, off);
            dx += __shfl_xor_sync(0xFFFFFFFFu, dx, off);
        }
        if (lane == 0)
            g_hsum[b * HH + j] = fmaxf(dm, 0.0f) + fmaxf(dx, 0.0f);
    }

    gridbar(NBLK);

    // ---- Phase C: a[] for channels [chunk*128, +128) --------------------
    {
        if (tid < HH) sh[tid] = g_hsum[b * HH + tid];
        __syncthreads();

        if (tid < 128) {
            const int c = chunk * 128 + tid;
            const float4* w1 = reinterpret_cast<const float4*>(W1 + c * HH);
            float acc = 0.0f;
            #pragma unroll
            for (int j = 0; j < HH / 4; j++) {
                float4 w = w1[j];
                acc += w.x * sh[j * 4 + 0] + w.y * sh[j * 4 + 1]
                     + w.z * sh[j * 4 + 2] + w.w * sh[j * 4 + 3];
            }
            g_a[b * CC + c] = 1.0f / (1.0f + expf(-acc));
        }
    }
}

// ---------------------------------------------------------------------------
// Kernel 3: out[b,s,c] = x[b,s,c] * a[b,c]   (float4 streaming, .cs hints)
// grid ((S*C/4)/256, B)
// ---------------------------------------------------------------------------
__global__ void k_scale(const float* __restrict__ x,
                        float*       __restrict__ out) {
    const int b = blockIdx.y;
    const unsigned i = blockIdx.x * blockDim.x + threadIdx.x;  // float4 idx
    const unsigned c4 = i & (CC / 4 - 1);                       // 0..255

    const size_t gi = (size_t)b * (SS * CC / 4) + i;
    float4 v = __ldcs(reinterpret_cast<const float4*>(x) + gi);
    float4 a = reinterpret_cast<const float4*>(g_a + b * CC)[c4];
    v.x *= a.x; v.y *= a.y; v.z *= a.z; v.w *= a.w;
    __stcs(reinterpret_cast<float4*>(out) + gi, v);
}

// ---------------------------------------------------------------------------
extern "C" void kernel_launch(void* const* d_in, const int* in_sizes, int n_in,
                              void* d_out, int out_size) {
    const float* x    = (const float*)d_in[0];   // [B,S,C]
    const int*   mask = (const int*)  d_in[1];   // [B,S]
    const float* W0   = (const float*)d_in[2];   // [H,C]
    const float* W1   = (const float*)d_in[3];   // [C,H]
    float*       out  = (float*)d_out;           // [B,S,C]

    (void)in_sizes; (void)n_in; (void)out_size;

    {   dim3 grid(NS, BB);                  k_partial<<<grid, 256>>>(x, mask); }
    {   dim3 grid(8, BB);                   k_tail   <<<grid, 256>>>(W0, W1);  }
    {   dim3 grid((SS * CC / 4) / 256, BB); k_scale  <<<grid, 256>>>(x, out);  }
}

// round 14
// speedup vs baseline: 1.0116x; 1.0116x over previous
#include <cuda_runtime.h>
#include <float.h>
#include <math.h>

// Problem constants (fixed by reference setup_inputs)
#define BB 8
#define SS 4096
#define CC 1024
#define HH 64
#define NS 128          // S splits for partial reduction
#define SROWS (SS/NS)   // 32 rows per partial chunk

// Scratch (no allocations allowed in kernel_launch)
__device__ float g_psum[BB*NS*CC];
__device__ float g_pmax[BB*NS*CC];
__device__ int   g_pcnt[BB*NS];
__device__ float g_mean[BB*CC];
__device__ float g_max [BB*CC];
__device__ float g_hsum[BB*HH];
__device__ float g_a   [BB*CC];
__device__ unsigned g_bar = 0;   // monotonic grid-barrier ticket counter

#define ACC(v)  do { \
    sum.x += (v).x; sum.y += (v).y; sum.z += (v).z; sum.w += (v).w; \
    mx.x = fmaxf(mx.x, (v).x); mx.y = fmaxf(mx.y, (v).y);           \
    mx.z = fmaxf(mx.z, (v).z); mx.w = fmaxf(mx.w, (v).w); } while (0)

#define ACCSM(s, m) do { \
    sum.x += (s).x; sum.y += (s).y; sum.z += (s).z; sum.w += (s).w; \
    mx.x = fmaxf(mx.x, (m).x); mx.y = fmaxf(mx.y, (m).y);           \
    mx.z = fmaxf(mx.z, (m).z); mx.w = fmaxf(mx.w, (m).w); } while (0)

// Software grid barrier for a co-resident grid of nb blocks.
__device__ __forceinline__ void gridbar(unsigned nb) {
    __syncthreads();
    __threadfence();
    if (threadIdx.x == 0) {
        const unsigned t = atomicAdd(&g_bar, 1u);
        const unsigned target = (t / nb + 1u) * nb;
        while (*((volatile unsigned*)&g_bar) < target) { }
    }
    __syncthreads();
}

#define CP_ASYNC16(dst_u32, src_ptr) \
    asm volatile("cp.async.cg.shared.global [%0], [%1], 16;\n" \
                 :: "r"(dst_u32), "l"(src_ptr))
#define CP_COMMIT() asm volatile("cp.async.commit_group;\n")
#define CP_WAIT1()  asm volatile("cp.async.wait_group 1;\n" ::: "memory")
#define CP_WAIT0()  asm volatile("cp.async.wait_group 0;\n" ::: "memory")

#define RB 4    // rows per pipeline batch

// ---------------------------------------------------------------------------
// Kernel 1: partial masked sum/max over a 32-row chunk, full 1024 channels.
// Ballot compaction; double-buffered cp.async pipeline (batch=4 rows,
// depth=2) so ~8 rows stay in flight with no drain bubble. Each thread
// copies/reduces only its own 16B slots -> no __syncthreads in the loop.
// grid (NS, BB) = 1024 blocks, 256 threads.
// ---------------------------------------------------------------------------
__global__ void k_partial(const float* __restrict__ x,
                          const int*   __restrict__ mask) {
    const int ns = blockIdx.x;
    const int b  = blockIdx.y;
    const int c4 = threadIdx.x;              // float4 index 0..255

    __shared__ int srows[SROWS];
    __shared__ int snv;
    __shared__ __align__(16) float buf[2][RB][CC];   // 32 KB
    const int s0 = ns * SROWS;

    if (threadIdx.x < 32) {
        const int lane = threadIdx.x;
        const int m = mask[b * SS + s0 + lane];
        const unsigned bal = __ballot_sync(0xFFFFFFFFu, m != 0);
        if (m) srows[__popc(bal & ((1u << lane) - 1u))] = lane;
        if (lane == 0) {
            snv = __popc(bal);
            g_pcnt[b * NS + ns] = __popc(bal);
        }
    }
    __syncthreads();
    const int nv = snv;

    float4 sum = make_float4(0.f, 0.f, 0.f, 0.f);
    float4 mx  = make_float4(-FLT_MAX, -FLT_MAX, -FLT_MAX, -FLT_MAX);

    const float* xbase = x + ((size_t)b * SS + s0) * CC;
    const unsigned sbase =
        (unsigned)__cvta_generic_to_shared(&buf[0][0][0]) + (unsigned)c4 * 16u;
    const unsigned stageBytes = RB * CC * 4u;

    const int nbatch = (nv + RB - 1) / RB;

    // prologue: issue batch 0
    if (nbatch > 0) {
        const int m0 = (nv < RB) ? nv : RB;
        #pragma unroll
        for (int r = 0; r < RB; r++)
            if (r < m0)
                CP_ASYNC16(sbase + (unsigned)r * (CC * 4u),
                           xbase + (size_t)srows[r] * CC + c4 * 4);
        CP_COMMIT();
    }

    for (int k = 0; k < nbatch; k++) {
        // issue batch k+1 into the other stage
        if (k + 1 < nbatch) {
            const int i1 = (k + 1) * RB;
            int m1 = nv - i1; if (m1 > RB) m1 = RB;
            const unsigned dst = sbase + ((k + 1) & 1) * stageBytes;
            #pragma unroll
            for (int r = 0; r < RB; r++)
                if (r < m1)
                    CP_ASYNC16(dst + (unsigned)r * (CC * 4u),
                               xbase + (size_t)srows[i1 + r] * CC + c4 * 4);
            CP_COMMIT();
            CP_WAIT1();             // batch k is complete, k+1 in flight
        } else {
            CP_WAIT0();             // last batch
        }

        const int i0 = k * RB;
        int m0 = nv - i0; if (m0 > RB) m0 = RB;
        const float (*stage)[CC] = buf[k & 1];
        #pragma unroll
        for (int r = 0; r < RB; r++) {
            if (r < m0) {
                float4 v = *reinterpret_cast<const float4*>(&stage[r][c4 * 4]);
                ACC(v);
            }
        }
    }

    reinterpret_cast<float4*>(g_psum + (b * NS + ns) * CC)[c4] = sum;
    reinterpret_cast<float4*>(g_pmax + (b * NS + ns) * CC)[c4] = mx;
}

// ---------------------------------------------------------------------------
// Kernel 2 (fused tail with grid barriers): fold -> MLP1 -> MLP2.
// grid (8, BB) = 64 blocks, 256 threads.  (R12-measured: ~5 us)
// ---------------------------------------------------------------------------
#define NBLK (8*BB)

__global__ void __launch_bounds__(256)
k_tail(const float* __restrict__ W0,     // [H, C]
       const float* __restrict__ W1) {   // [C, H]
    const int chunk = blockIdx.x;        // 0..7
    const int b     = blockIdx.y;
    const int tid   = threadIdx.x;
    const int warp  = tid >> 5;
    const int lane  = tid & 31;

    __shared__ float4 ssum[8][32];
    __shared__ float4 smax4[8][32];
    __shared__ __align__(16) float smean[CC];
    __shared__ __align__(16) float smaxv[CC];
    __shared__ __align__(16) float sh[HH];
    __shared__ float  scount;

    // ---- Phase A: fold NS=128 partials for channels [chunk*128, +128) ----
    {
        const int g  = tid & 31;
        const int sl = tid >> 5;
        const int c4 = chunk * 32 + g;

        float4 sum = make_float4(0.f, 0.f, 0.f, 0.f);
        float4 mx  = make_float4(-FLT_MAX, -FLT_MAX, -FLT_MAX, -FLT_MAX);
        const float4* ps = reinterpret_cast<const float4*>(
            g_psum + (b * NS + sl * 16) * CC) + c4;
        const float4* pm = reinterpret_cast<const float4*>(
            g_pmax + (b * NS + sl * 16) * CC) + c4;
        #pragma unroll
        for (int k = 0; k < 16; k++) {
            float4 s = ps[(size_t)k * (CC / 4)];
            float4 m = pm[(size_t)k * (CC / 4)];
            ACCSM(s, m);
        }
        ssum[sl][g]  = sum;
        smax4[sl][g] = mx;

        if (tid < 32) {
            const int* pc = g_pcnt + b * NS;
            int c = pc[lane] + pc[lane + 32] + pc[lane + 64] + pc[lane + 96];
            #pragma unroll
            for (int off = 16; off > 0; off >>= 1)
                c += __shfl_xor_sync(0xFFFFFFFFu, c, off);
            if (lane == 0) scount = fmaxf((float)c, 1.0f);
        }
        __syncthreads();

        if (tid < 32) {
            const int g0 = tid;
            float4 sum2 = ssum[0][g0];
            float4 mx2  = smax4[0][g0];
            #pragma unroll
            for (int k = 1; k < 8; k++) {
                float4 s = ssum[k][g0];
                float4 m = smax4[k][g0];
                sum2.x += s.x; sum2.y += s.y; sum2.z += s.z; sum2.w += s.w;
                mx2.x = fmaxf(mx2.x, m.x); mx2.y = fmaxf(mx2.y, m.y);
                mx2.z = fmaxf(mx2.z, m.z); mx2.w = fmaxf(mx2.w, m.w);
            }
            const float inv = 1.0f / scount;
            sum2.x *= inv; sum2.y *= inv; sum2.z *= inv; sum2.w *= inv;
            reinterpret_cast<float4*>(g_mean + b * CC)[chunk * 32 + g0] = sum2;
            reinterpret_cast<float4*>(g_max  + b * CC)[chunk * 32 + g0] = mx2;
        }
    }

    gridbar(NBLK);

    // ---- Phase B: hidden units j = chunk*8 + warp for batch b -----------
    {
        {
            float4 S = reinterpret_cast<const float4*>(g_mean + b * CC)[tid];
            float4 M = reinterpret_cast<const float4*>(g_max  + b * CC)[tid];
            reinterpret_cast<float4*>(smean)[tid] = S;
            reinterpret_cast<float4*>(smaxv)[tid] = M;
        }
        __syncthreads();

        const int j = chunk * 8 + warp;
        const float* w = W0 + j * CC;
        float dm = 0.0f, dx = 0.0f;
        #pragma unroll 8
        for (int k = lane; k < CC; k += 32) {
            float wv = w[k];
            dm += wv * smean[k];
            dx += wv * smaxv[k];
        }
        #pragma unroll
        for (int off = 16; off > 0; off >>= 1) {
            dm += __shfl_xor_sync(0xFFFFFFFFu, dm, off);
            dx += __shfl_xor_sync(0xFFFFFFFFu, dx, off);
        }
        if (lane == 0)
            g_hsum[b * HH + j] = fmaxf(dm, 0.0f) + fmaxf(dx, 0.0f);
    }

    gridbar(NBLK);

    // ---- Phase C: a[] for channels [chunk*128, +128) --------------------
    {
        if (tid < HH) sh[tid] = g_hsum[b * HH + tid];
        __syncthreads();

        if (tid < 128) {
            const int c = chunk * 128 + tid;
            const float4* w1 = reinterpret_cast<const float4*>(W1 + c * HH);
            float acc = 0.0f;
            #pragma unroll
            for (int j = 0; j < HH / 4; j++) {
                float4 w = w1[j];
                acc += w.x * sh[j * 4 + 0] + w.y * sh[j * 4 + 1]
                     + w.z * sh[j * 4 + 2] + w.w * sh[j * 4 + 3];
            }
            g_a[b * CC + c] = 1.0f / (1.0f + expf(-acc));
        }
    }
}

// ---------------------------------------------------------------------------
// Kernel 3: out[b,s,c] = x[b,s,c] * a[b,c]   (float4 streaming, .cs hints)
// grid ((S*C/4)/256, B)
// ---------------------------------------------------------------------------
__global__ void k_scale(const float* __restrict__ x,
                        float*       __restrict__ out) {
    const int b = blockIdx.y;
    const unsigned i = blockIdx.x * blockDim.x + threadIdx.x;  // float4 idx
    const unsigned c4 = i & (CC / 4 - 1);                       // 0..255

    const size_t gi = (size_t)b * (SS * CC / 4) + i;
    float4 v = __ldcs(reinterpret_cast<const float4*>(x) + gi);
    float4 a = reinterpret_cast<const float4*>(g_a + b * CC)[c4];
    v.x *= a.x; v.y *= a.y; v.z *= a.z; v.w *= a.w;
    __stcs(reinterpret_cast<float4*>(out) + gi, v);
}

// ---------------------------------------------------------------------------
extern "C" void kernel_launch(void* const* d_in, const int* in_sizes, int n_in,
                              void* d_out, int out_size) {
    const float* x    = (const float*)d_in[0];   // [B,S,C]
    const int*   mask = (const int*)  d_in[1];   // [B,S]
    const float* W0   = (const float*)d_in[2];   // [H,C]
    const float* W1   = (const float*)d_in[3];   // [C,H]
    float*       out  = (float*)d_out;           // [B,S,C]

    (void)in_sizes; (void)n_in; (void)out_size;

    {   dim3 grid(NS, BB);                  k_partial<<<grid, 256>>>(x, mask); }
    {   dim3 grid(8, BB);                   k_tail   <<<grid, 256>>>(W0, W1);  }
    {   dim3 grid((SS * CC / 4) / 256, BB); k_scale  <<<grid, 256>>>(x, out);  }
}